// round 1
// baseline (speedup 1.0000x reference)
#include <cuda_runtime.h>
#include <cstdint>

// ---------------------------------------------------------------------------
// VectorQuantizer: fused distance-GEMM + argmin + gather + loss
//   inputs:  d_in[0] = inputs  [64*512, 256] f32  (N*D = 8388608)
//            d_in[1] = emb_w   [8192, 256]   f32
//   output:  d_out[0 .. N*D)   = quantized_st (== codebook gather, fp32)
//            d_out[N*D]        = loss = 1.25 * mean((q - clip(x))^2)
// ---------------------------------------------------------------------------

#define D_DIM      256
#define BM         64        // rows per CTA
#define BN         128       // codes per K-tile
#define BD         32        // D chunk
#define NTHREADS   256
#define ES_STRIDE  132       // 128 + 4 pad (floats), keeps 16B alignment (528B rows)

__device__ float g_enorm[8192];
__device__ float g_partials[512];

#define FMA_F32X2(acc, a, b) \
    asm("fma.rn.f32x2 %0, %1, %2, %0;" : "+l"(acc) : "l"(a), "l"(b))

#define UNPACK_F32X2(lo, hi, v) \
    asm("mov.b64 {%0, %1}, %2;" : "=f"(lo), "=f"(hi) : "l"(v))

// --------------------------- ||e_k||^2 precompute ---------------------------
__global__ void vq_enorm_kernel(const float* __restrict__ emb, int K) {
    int k = blockIdx.x * blockDim.x + threadIdx.x;
    if (k >= K) return;
    const float4* r = (const float4*)(emb + (size_t)k * D_DIM);
    float s = 0.0f;
#pragma unroll
    for (int i = 0; i < D_DIM / 4; i++) {
        float4 v = r[i];
        s += v.x * v.x + v.y * v.y + v.z * v.z + v.w * v.w;
    }
    g_enorm[k] = s;
}

// ------------------------------- main kernel --------------------------------
// smem layout (floats):
//   xsd  [256][128]      : clipped X tile, row-duplicated (d-major), 32768 f
//   es   [32][ES_STRIDE] : E chunk transposed (d-major), 4224 f
//   rbv  [64][16]        : per-thread best value, 1024 f
//   rbi  [64][16]  (int) : per-thread best index, 1024 i
//   ridx [64]      (int) : final per-row argmin
#define SM_XS    (D_DIM * 2 * BM)             // 32768
#define SM_ES    (BD * ES_STRIDE)             // 4224
#define SM_RBV   (BM * 16)                    // 1024
#define SM_RBI   (BM * 16)                    // 1024
#define SM_RIDX  (BM)                         // 64
#define SMEM_FLOATS (SM_XS + SM_ES + SM_RBV + SM_RBI + SM_RIDX)
#define SMEM_BYTES  (SMEM_FLOATS * 4)

__global__ __launch_bounds__(NTHREADS, 1)
void vq_main_kernel(const float* __restrict__ xg,
                    const float* __restrict__ emb,
                    float* __restrict__ out,
                    int K) {
    extern __shared__ float sm[];
    float* xsd  = sm;
    float* es   = sm + SM_XS;
    float* rbv  = es + SM_ES;
    int*   rbi  = (int*)(rbv + SM_RBV);
    int*   ridx = rbi + SM_RBI;

    const int tid = threadIdx.x;
    const int tx  = tid & 15;      // 0..15 : code sub-block (8 codes)
    const int ty  = tid >> 4;      // 0..15 : row sub-block (4 rows)
    const int row0 = blockIdx.x * BM;

    // ---- load, clip, duplicate-transpose X tile ----
    // i indexes float4 units: 64 rows x 64 f4/row = 4096
    for (int i = tid; i < BM * (D_DIM / 4); i += NTHREADS) {
        int r  = i >> 6;
        int c4 = i & 63;
        float4 v = *(const float4*)(xg + (size_t)(row0 + r) * D_DIM + c4 * 4);
        v.x = fminf(fmaxf(v.x, -1.0f), 1.0f);
        v.y = fminf(fmaxf(v.y, -1.0f), 1.0f);
        v.z = fminf(fmaxf(v.z, -1.0f), 1.0f);
        v.w = fminf(fmaxf(v.w, -1.0f), 1.0f);
        float* xp = xsd + (c4 * 4) * (2 * BM) + 2 * r;
        xp[0]   = v.x;  xp[1]   = v.x;
        xp[128] = v.y;  xp[129] = v.y;
        xp[256] = v.z;  xp[257] = v.z;
        xp[384] = v.w;  xp[385] = v.w;
    }
    __syncthreads();

    unsigned long long acc[4][4];
    float best[4];
    int   bidx[4];
#pragma unroll
    for (int i = 0; i < 4; i++) { best[i] = 3.0e38f; bidx[i] = 0; }

    const int ktiles = K >> 7;   // K / 128
    for (int kt = 0; kt < ktiles; ++kt) {
#pragma unroll
        for (int i = 0; i < 4; i++)
#pragma unroll
            for (int p = 0; p < 4; p++) acc[i][p] = 0ULL;

        for (int dc = 0; dc < D_DIM / BD; ++dc) {
            // ---- load E chunk [128 codes x 32 d], transposed into es ----
#pragma unroll
            for (int l = 0; l < 4; l++) {
                int idx  = l * NTHREADS + tid;       // 1024 float4 units
                int code = idx >> 3;
                int c4   = idx & 7;
                float4 v = *(const float4*)(emb
                          + (size_t)(kt * BN + code) * D_DIM + dc * BD + c4 * 4);
                float* ep = es + (c4 * 4) * ES_STRIDE + code;
                ep[0]              = v.x;
                ep[ES_STRIDE]      = v.y;
                ep[2 * ES_STRIDE]  = v.z;
                ep[3 * ES_STRIDE]  = v.w;
            }
            __syncthreads();

#pragma unroll
            for (int d = 0; d < BD; ++d) {
                const unsigned long long* ap =
                    (const unsigned long long*)(xsd + (dc * BD + d) * (2 * BM));
                unsigned long long a0 = ap[ty * 4 + 0];
                unsigned long long a1 = ap[ty * 4 + 1];
                unsigned long long a2 = ap[ty * 4 + 2];
                unsigned long long a3 = ap[ty * 4 + 3];
                const float* eb = es + d * ES_STRIDE + tx * 8;
                ulonglong2 b01 = *(const ulonglong2*)(eb);
                ulonglong2 b23 = *(const ulonglong2*)(eb + 4);

                FMA_F32X2(acc[0][0], a0, b01.x); FMA_F32X2(acc[0][1], a0, b01.y);
                FMA_F32X2(acc[0][2], a0, b23.x); FMA_F32X2(acc[0][3], a0, b23.y);
                FMA_F32X2(acc[1][0], a1, b01.x); FMA_F32X2(acc[1][1], a1, b01.y);
                FMA_F32X2(acc[1][2], a1, b23.x); FMA_F32X2(acc[1][3], a1, b23.y);
                FMA_F32X2(acc[2][0], a2, b01.x); FMA_F32X2(acc[2][1], a2, b01.y);
                FMA_F32X2(acc[2][2], a2, b23.x); FMA_F32X2(acc[2][3], a2, b23.y);
                FMA_F32X2(acc[3][0], a3, b01.x); FMA_F32X2(acc[3][1], a3, b01.y);
                FMA_F32X2(acc[3][2], a3, b23.x); FMA_F32X2(acc[3][3], a3, b23.y);
            }
            __syncthreads();
        }

        // ---- per-K-tile argmin update (ascending code order, strict <) ----
        float en[8];
#pragma unroll
        for (int j = 0; j < 8; j++) en[j] = g_enorm[(kt << 7) + (tx << 3) + j];
#pragma unroll
        for (int i = 0; i < 4; i++) {
#pragma unroll
            for (int p = 0; p < 4; p++) {
                float s0, s1;
                UNPACK_F32X2(s0, s1, acc[i][p]);
                int k0 = (kt << 7) + (tx << 3) + 2 * p;
                float sc0 = en[2 * p]     - 2.0f * s0;
                float sc1 = en[2 * p + 1] - 2.0f * s1;
                if (sc0 < best[i]) { best[i] = sc0; bidx[i] = k0; }
                if (sc1 < best[i]) { best[i] = sc1; bidx[i] = k0 + 1; }
            }
        }
    }

    // ---- cross-thread argmin reduction (ascending tx = ascending codes) ----
#pragma unroll
    for (int i = 0; i < 4; i++) {
        int row = ty * 4 + i;
        rbv[row * 16 + tx] = best[i];
        rbi[row * 16 + tx] = bidx[i];
    }
    __syncthreads();
    if (tid < BM) {
        float bv = rbv[tid * 16];
        int   bi = rbi[tid * 16];
        for (int t = 1; t < 16; t++) {
            float v = rbv[tid * 16 + t];
            if (v < bv) { bv = v; bi = rbi[tid * 16 + t]; }
        }
        ridx[tid] = bi;
    }
    __syncthreads();

    // ---- gather + straight-through output + loss partial ----
    float errsum = 0.0f;
    for (int i = tid; i < BM * (D_DIM / 4); i += NTHREADS) {
        int r  = i >> 6;
        int c4 = i & 63;
        int k  = ridx[r];
        float4 q = *(const float4*)(emb + (size_t)k * D_DIM + c4 * 4);
        const float* xp = xsd + (c4 * 4) * (2 * BM) + 2 * r;
        float4 o;
        float xv, dv;
        xv = xp[0];   dv = q.x - xv; o.x = xv + dv; errsum += dv * dv;
        xv = xp[128]; dv = q.y - xv; o.y = xv + dv; errsum += dv * dv;
        xv = xp[256]; dv = q.z - xv; o.z = xv + dv; errsum += dv * dv;
        xv = xp[384]; dv = q.w - xv; o.w = xv + dv; errsum += dv * dv;
        *(float4*)(out + (size_t)(row0 + r) * D_DIM + c4 * 4) = o;
    }

    // deterministic block tree-reduction of errsum (reuse rbv region)
    __syncthreads();
    float* red = rbv;
    red[tid] = errsum;
    __syncthreads();
    for (int s = NTHREADS / 2; s > 0; s >>= 1) {
        if (tid < s) red[tid] += red[tid + s];
        __syncthreads();
    }
    if (tid == 0) g_partials[blockIdx.x] = red[0];
}

// ------------------------------- loss finalize ------------------------------
__global__ void vq_loss_kernel(float* __restrict__ out, int nblocks,
                               int ND, int out_size) {
    __shared__ float red[NTHREADS];
    int tid = threadIdx.x;
    float s = 0.0f;
    for (int i = tid; i < nblocks; i += NTHREADS) s += g_partials[i];
    red[tid] = s;
    __syncthreads();
    for (int st = NTHREADS / 2; st > 0; st >>= 1) {
        if (tid < st) red[tid] += red[tid + st];
        __syncthreads();
    }
    if (tid == 0 && out_size > ND)
        out[ND] = 1.25f * (red[0] / (float)ND);
    // zero-fill any remaining poisoned tail
    for (int i = ND + 1 + tid; i < out_size; i += NTHREADS) out[i] = 0.0f;
}

// --------------------------------- launch -----------------------------------
extern "C" void kernel_launch(void* const* d_in, const int* in_sizes, int n_in,
                              void* d_out, int out_size) {
    const float* x   = (const float*)d_in[0];
    const float* emb = (const float*)d_in[1];
    float* out = (float*)d_out;

    int ND    = in_sizes[0];          // 8388608
    int K     = in_sizes[1] / D_DIM;  // 8192
    int nrows = ND / D_DIM;           // 32768
    int nblk  = nrows / BM;           // 512

    cudaFuncSetAttribute(vq_main_kernel,
                         cudaFuncAttributeMaxDynamicSharedMemorySize,
                         SMEM_BYTES);

    vq_enorm_kernel<<<(K + NTHREADS - 1) / NTHREADS, NTHREADS>>>(emb, K);
    vq_main_kernel<<<nblk, NTHREADS, SMEM_BYTES>>>(x, emb, out, K);
    vq_loss_kernel<<<1, NTHREADS>>>(out, nblk, ND, out_size);
}

// round 3
// speedup vs baseline: 3.8319x; 3.8319x over previous
#include <cuda_runtime.h>
#include <cuda_bf16.h>
#include <cstdint>

// ===========================================================================
// VectorQuantizer on GB300 (sm_103 family target, no tcgen05 available):
// split-bf16 3-pass distance GEMM via mma.sync.m16n8k16 + fused top-2 argmin,
// exact fp32 fixup, straight-through output + loss.
// ===========================================================================

#define NROWS    32768
#define DDIM     256
#define KCODES   8192
#define ROWTILE  128
#define NCTAS    (NROWS / ROWTILE)      // 256
#define NTILES   (KCODES / 128)         // 64
#define THREADS  256
#define FIXWARPS 8
#define FIXBLOCKS (NROWS / FIXWARPS)    // 4096

// SMEM layout (bytes):
//   Xhi [128][264] bf16 @ 0        (row stride 528B)   67584
//   Xlo [128][264] bf16 @ 67584                        67584
//   E ring @ 135168: stage s (0/1) at s*36864:
//       Ehi [128][72] bf16 (stride 144B) 18432, Elo +18432
//   total 208896
#define XHI_OFF   0
#define XLO_OFF   67584
#define E_OFF     135168
#define SMEM_DYN  208896
#define SX        528     // X row stride bytes
#define SE        144     // E row stride bytes

__device__ unsigned short g_Xhi[NROWS * DDIM];
__device__ unsigned short g_Xlo[NROWS * DDIM];
__device__ unsigned short g_Ehi[KCODES * DDIM];
__device__ unsigned short g_Elo[KCODES * DDIM];
__device__ float g_enorm[KCODES];
__device__ int   g_i1[NROWS];
__device__ int   g_i2[NROWS];
__device__ float g_part[FIXBLOCKS];

// ------------------------------ PTX helpers ---------------------------------
__device__ __forceinline__ uint32_t smem_u32(const void* p) {
    uint32_t a;
    asm("{ .reg .u64 t; cvta.to.shared.u64 t, %1; cvt.u32.u64 %0, t; }"
        : "=r"(a) : "l"(p));
    return a;
}

__device__ __forceinline__ void ldsm4(uint32_t* r, uint32_t addr) {
    asm volatile("ldmatrix.sync.aligned.m8n8.x4.shared.b16 {%0,%1,%2,%3}, [%4];"
                 : "=r"(r[0]), "=r"(r[1]), "=r"(r[2]), "=r"(r[3]) : "r"(addr));
}

__device__ __forceinline__ void mma_bf16(float* d, const uint32_t* a,
                                         const uint32_t* b) {
    asm volatile(
        "mma.sync.aligned.m16n8k16.row.col.f32.bf16.bf16.f32 "
        "{%0,%1,%2,%3}, {%4,%5,%6,%7}, {%8,%9}, {%0,%1,%2,%3};"
        : "+f"(d[0]), "+f"(d[1]), "+f"(d[2]), "+f"(d[3])
        : "r"(a[0]), "r"(a[1]), "r"(a[2]), "r"(a[3]), "r"(b[0]), "r"(b[1]));
}

__device__ __forceinline__ void cpasync16(uint32_t dst, const void* src) {
    asm volatile("cp.async.cg.shared.global [%0], [%1], 16;"
                 :: "r"(dst), "l"(src));
}
#define CP_COMMIT() asm volatile("cp.async.commit_group;" ::: "memory")
#define CP_WAIT0()  asm volatile("cp.async.wait_group 0;" ::: "memory")

// top-2 insert: strict < keeps earliest index; equal value prefers lower index
__device__ __forceinline__ void t2_ins(float& v1, int& i1, float& v2, int& i2,
                                       float v, int i) {
    if (v < v1 || (v == v1 && i < i1)) { v2 = v1; i2 = i1; v1 = v; i1 = i; }
    else if (v < v2 || (v == v2 && i < i2)) { v2 = v; i2 = i; }
}

// ------------------------------- split kernels ------------------------------
__global__ void vq_split_x(const float4* __restrict__ in, int n4) {
    int i = blockIdx.x * blockDim.x + threadIdx.x;
    if (i >= n4) return;
    float4 v = in[i];
    float f[4] = {fminf(fmaxf(v.x, -1.f), 1.f), fminf(fmaxf(v.y, -1.f), 1.f),
                  fminf(fmaxf(v.z, -1.f), 1.f), fminf(fmaxf(v.w, -1.f), 1.f)};
    unsigned short h[4], l[4];
#pragma unroll
    for (int j = 0; j < 4; j++) {
        __nv_bfloat16 hb = __float2bfloat16(f[j]);
        h[j] = __bfloat16_as_ushort(hb);
        l[j] = __bfloat16_as_ushort(__float2bfloat16(f[j] - __bfloat162float(hb)));
    }
    ((uint2*)g_Xhi)[i] = make_uint2(h[0] | ((uint32_t)h[1] << 16), h[2] | ((uint32_t)h[3] << 16));
    ((uint2*)g_Xlo)[i] = make_uint2(l[0] | ((uint32_t)l[1] << 16), l[2] | ((uint32_t)l[3] << 16));
}

__global__ void vq_split_e(const float4* __restrict__ in, int n4) {
    int i = blockIdx.x * blockDim.x + threadIdx.x;
    if (i >= n4) return;
    float4 v = in[i];
    float f[4] = {v.x, v.y, v.z, v.w};
    unsigned short h[4], l[4];
#pragma unroll
    for (int j = 0; j < 4; j++) {
        __nv_bfloat16 hb = __float2bfloat16(f[j]);
        h[j] = __bfloat16_as_ushort(hb);
        l[j] = __bfloat16_as_ushort(__float2bfloat16(f[j] - __bfloat162float(hb)));
    }
    ((uint2*)g_Ehi)[i] = make_uint2(h[0] | ((uint32_t)h[1] << 16), h[2] | ((uint32_t)h[3] << 16));
    ((uint2*)g_Elo)[i] = make_uint2(l[0] | ((uint32_t)l[1] << 16), l[2] | ((uint32_t)l[3] << 16));
}

__global__ void vq_enorm_kernel(const float* __restrict__ emb, int K) {
    int k = blockIdx.x * blockDim.x + threadIdx.x;
    if (k >= K) return;
    const float4* r = (const float4*)(emb + (size_t)k * DDIM);
    float s = 0.0f;
#pragma unroll
    for (int i = 0; i < DDIM / 4; i++) {
        float4 v = r[i];
        s += v.x * v.x + v.y * v.y + v.z * v.z + v.w * v.w;
    }
    g_enorm[k] = s;
}

// --------------------------------- main kernel ------------------------------
__global__ __launch_bounds__(THREADS, 1)
void vq_main_kernel() {
    extern __shared__ char sm[];
    const uint32_t smB = smem_u32(sm);

    const int tid   = threadIdx.x;
    const int lane  = tid & 31;
    const int wid   = tid >> 5;
    const int warp_m = wid >> 2;        // 0..1  (64 rows each)
    const int warp_n = wid & 3;         // 0..3  (32 codes each)
    const int row0  = blockIdx.x * ROWTILE;

    // ---- load resident X tile (hi+lo), padded stride ----
    {
        const uint4* ph = (const uint4*)g_Xhi + (size_t)row0 * 32;
        const uint4* pl = (const uint4*)g_Xlo + (size_t)row0 * 32;
        for (int i = tid; i < 4096; i += THREADS) {
            int r = i >> 5, q = i & 31;
            *(uint4*)(sm + XHI_OFF + r * SX + q * 16) = ph[r * 32 + q];
            *(uint4*)(sm + XLO_OFF + r * SX + q * 16) = pl[r * 32 + q];
        }
    }

    // ---- cp.async E chunk issue ----
    auto issueE = [&](int stage, int t, int kc) {
#pragma unroll
        for (int j = 0; j < 8; j++) {
            int i = tid + j * THREADS;            // 0..2047
            int variant = i >> 10;                // 0=hi 1=lo
            int idx = i & 1023;
            int r = idx >> 3, q = idx & 7;
            size_t soff = ((size_t)(t * 128 + r) * DDIM + kc * 64 + q * 8) * 2;
            const char* src = (variant ? (const char*)g_Elo
                                       : (const char*)g_Ehi) + soff;
            uint32_t dst = smB + E_OFF + stage * 36864 + variant * 18432
                         + r * SE + q * 16;
            cpasync16(dst, src);
        }
        CP_COMMIT();
    };

    issueE(0, 0, 0);

    // ldmatrix address bases (bytes)
    const uint32_t aOff = (uint32_t)(warp_m * 64 + (lane & 15)) * SX
                        + ((lane >> 4) << 4);
    const uint32_t bOff = (uint32_t)(warp_n * 32 + (lane & 7) + ((lane >> 4) << 3)) * SE
                        + (((lane >> 3) & 1) << 4);

    float acc[4][4][4];
    float t2v[8][2];
    int   t2i[8][2];
#pragma unroll
    for (int r = 0; r < 8; r++) {
        t2v[r][0] = 3.4e38f; t2v[r][1] = 3.4e38f;
        t2i[r][0] = 0;       t2i[r][1] = 0;
    }

    for (int t = 0; t < NTILES; ++t) {
#pragma unroll
        for (int mt = 0; mt < 4; mt++)
#pragma unroll
            for (int nt = 0; nt < 4; nt++)
#pragma unroll
                for (int rr = 0; rr < 4; rr++) acc[mt][nt][rr] = 0.f;

        for (int kc = 0; kc < 4; ++kc) {
            int idx = t * 4 + kc;
            CP_WAIT0();
            __syncthreads();
            if (idx + 1 < NTILES * 4)
                issueE((idx + 1) & 1, (idx + 1) >> 2, (idx + 1) & 3);

            int stage = idx & 1;
            const uint32_t eHi = smB + E_OFF + stage * 36864;
            const uint32_t eLo = eHi + 18432;

#pragma unroll
            for (int ks = 0; ks < 4; ++ks) {
                uint32_t ah[4][4], al[4][4];
                uint32_t bh[4][2], bl[4][2];
                const uint32_t akb = (uint32_t)(kc * 64 + ks * 16) * 2;
#pragma unroll
                for (int mt = 0; mt < 4; mt++) {
                    ldsm4(ah[mt], smB + XHI_OFF + aOff + mt * (16 * SX) + akb);
                    ldsm4(al[mt], smB + XLO_OFF + aOff + mt * (16 * SX) + akb);
                }
#pragma unroll
                for (int ntp = 0; ntp < 2; ntp++) {
                    uint32_t r4[4];
                    ldsm4(r4, eHi + bOff + ntp * (16 * SE) + ks * 32);
                    bh[ntp * 2][0] = r4[0]; bh[ntp * 2][1] = r4[1];
                    bh[ntp * 2 + 1][0] = r4[2]; bh[ntp * 2 + 1][1] = r4[3];
                    ldsm4(r4, eLo + bOff + ntp * (16 * SE) + ks * 32);
                    bl[ntp * 2][0] = r4[0]; bl[ntp * 2][1] = r4[1];
                    bl[ntp * 2 + 1][0] = r4[2]; bl[ntp * 2 + 1][1] = r4[3];
                }
#pragma unroll
                for (int mt = 0; mt < 4; mt++)
#pragma unroll
                    for (int nt = 0; nt < 4; nt++) {
                        mma_bf16(acc[mt][nt], ah[mt], bh[nt]);
                        mma_bf16(acc[mt][nt], al[mt], bh[nt]);
                        mma_bf16(acc[mt][nt], ah[mt], bl[nt]);
                    }
            }
        }

        // ---- per-tile epilogue: score + top-2 ----
#pragma unroll
        for (int nt = 0; nt < 4; nt++) {
            int cbase = t * 128 + warp_n * 32 + nt * 8 + 2 * (lane & 3);
            float e0 = g_enorm[cbase];
            float e1 = g_enorm[cbase + 1];
#pragma unroll
            for (int mt = 0; mt < 4; mt++)
#pragma unroll
                for (int h = 0; h < 2; h++) {
                    int tr = mt * 2 + h;
                    float s0 = fmaf(-2.f, acc[mt][nt][h * 2 + 0], e0);
                    float s1 = fmaf(-2.f, acc[mt][nt][h * 2 + 1], e1);
                    t2_ins(t2v[tr][0], t2i[tr][0], t2v[tr][1], t2i[tr][1], s0, cbase);
                    t2_ins(t2v[tr][0], t2i[tr][0], t2v[tr][1], t2i[tr][1], s1, cbase + 1);
                }
        }
    }

    // ---- merge across the 4 lanes sharing each row ----
    __syncthreads();   // done with E smem; reuse as scratch
#pragma unroll
    for (int tr = 0; tr < 8; tr++) {
        float v1 = t2v[tr][0], v2 = t2v[tr][1];
        int   i1 = t2i[tr][0], i2 = t2i[tr][1];
#pragma unroll
        for (int o = 1; o <= 2; o <<= 1) {
            float w1 = __shfl_xor_sync(0xFFFFFFFFu, v1, o);
            float w2 = __shfl_xor_sync(0xFFFFFFFFu, v2, o);
            int   j1 = __shfl_xor_sync(0xFFFFFFFFu, i1, o);
            int   j2 = __shfl_xor_sync(0xFFFFFFFFu, i2, o);
            t2_ins(v1, i1, v2, i2, w1, j1);
            t2_ins(v1, i1, v2, i2, w2, j2);
        }
        if ((lane & 3) == 0) {
            int mt = tr >> 1, h = tr & 1;
            int rloc = warp_m * 64 + mt * 16 + h * 8 + (lane >> 2);
            uint4 pk;
            pk.x = __float_as_uint(v1); pk.y = (uint32_t)i1;
            pk.z = __float_as_uint(v2); pk.w = (uint32_t)i2;
            *(uint4*)(sm + E_OFF + (rloc * 4 + warp_n) * 16) = pk;
        }
    }
    __syncthreads();

    // ---- final per-row merge over 4 N-warps ----
    if (tid < ROWTILE) {
        float v1 = 3.4e38f, v2 = 3.4e38f;
        int   i1 = 0, i2 = 0;
#pragma unroll
        for (int w = 0; w < 4; w++) {
            uint4 pk = *(const uint4*)(sm + E_OFF + (tid * 4 + w) * 16);
            t2_ins(v1, i1, v2, i2, __uint_as_float(pk.x), (int)pk.y);
            t2_ins(v1, i1, v2, i2, __uint_as_float(pk.z), (int)pk.w);
        }
        g_i1[row0 + tid] = i1;
        g_i2[row0 + tid] = i2;
    }
}

// ------------------------- exact fixup + output + loss ----------------------
__global__ __launch_bounds__(256, 4)
void vq_fixup_kernel(const float* __restrict__ x, const float* __restrict__ emb,
                     float* __restrict__ out) {
    __shared__ float werr[FIXWARPS];
    int wid = threadIdx.x >> 5, lane = threadIdx.x & 31;
    int row = blockIdx.x * FIXWARPS + wid;

    const float4* xr = (const float4*)(x + (size_t)row * DDIM) + lane * 2;
    float4 xa = xr[0], xb = xr[1];
    xa.x = fminf(fmaxf(xa.x, -1.f), 1.f); xa.y = fminf(fmaxf(xa.y, -1.f), 1.f);
    xa.z = fminf(fmaxf(xa.z, -1.f), 1.f); xa.w = fminf(fmaxf(xa.w, -1.f), 1.f);
    xb.x = fminf(fmaxf(xb.x, -1.f), 1.f); xb.y = fminf(fmaxf(xb.y, -1.f), 1.f);
    xb.z = fminf(fmaxf(xb.z, -1.f), 1.f); xb.w = fminf(fmaxf(xb.w, -1.f), 1.f);

    int i1 = g_i1[row], i2 = g_i2[row];
    const float4* e1r = (const float4*)(emb + (size_t)i1 * DDIM) + lane * 2;
    const float4* e2r = (const float4*)(emb + (size_t)i2 * DDIM) + lane * 2;
    float4 e1a = e1r[0], e1b = e1r[1];
    float4 e2a = e2r[0], e2b = e2r[1];

    float p1 = 0.f, p2 = 0.f;
#define ACC(p, ev, xv) p = fmaf(ev, ev, p); p = fmaf(-2.f * (xv), ev, p)
    ACC(p1, e1a.x, xa.x); ACC(p1, e1a.y, xa.y); ACC(p1, e1a.z, xa.z); ACC(p1, e1a.w, xa.w);
    ACC(p1, e1b.x, xb.x); ACC(p1, e1b.y, xb.y); ACC(p1, e1b.z, xb.z); ACC(p1, e1b.w, xb.w);
    ACC(p2, e2a.x, xa.x); ACC(p2, e2a.y, xa.y); ACC(p2, e2a.z, xa.z); ACC(p2, e2a.w, xa.w);
    ACC(p2, e2b.x, xb.x); ACC(p2, e2b.y, xb.y); ACC(p2, e2b.z, xb.z); ACC(p2, e2b.w, xb.w);
#undef ACC
#pragma unroll
    for (int o = 16; o > 0; o >>= 1) {
        p1 += __shfl_xor_sync(0xFFFFFFFFu, p1, o);
        p2 += __shfl_xor_sync(0xFFFFFFFFu, p2, o);
    }
    bool use2 = (p2 < p1) || (p2 == p1 && i2 < i1);
    float4 qa = use2 ? e2a : e1a;
    float4 qb = use2 ? e2b : e1b;

    float err = 0.f;
    float4 oa, ob, d;
    d.x = qa.x - xa.x; d.y = qa.y - xa.y; d.z = qa.z - xa.z; d.w = qa.w - xa.w;
    oa.x = xa.x + d.x; oa.y = xa.y + d.y; oa.z = xa.z + d.z; oa.w = xa.w + d.w;
    err += d.x * d.x + d.y * d.y + d.z * d.z + d.w * d.w;
    d.x = qb.x - xb.x; d.y = qb.y - xb.y; d.z = qb.z - xb.z; d.w = qb.w - xb.w;
    ob.x = xb.x + d.x; ob.y = xb.y + d.y; ob.z = xb.z + d.z; ob.w = xb.w + d.w;
    err += d.x * d.x + d.y * d.y + d.z * d.z + d.w * d.w;

    float4* orow = (float4*)(out + (size_t)row * DDIM) + lane * 2;
    orow[0] = oa;
    orow[1] = ob;

#pragma unroll
    for (int o = 16; o > 0; o >>= 1) err += __shfl_xor_sync(0xFFFFFFFFu, err, o);
    if (lane == 0) werr[wid] = err;
    __syncthreads();
    if (threadIdx.x == 0) {
        float s = 0.f;
#pragma unroll
        for (int w = 0; w < FIXWARPS; w++) s += werr[w];
        g_part[blockIdx.x] = s;
    }
}

__global__ void vq_loss_kernel(float* __restrict__ out, int ND, int out_size) {
    __shared__ float red[256];
    int tid = threadIdx.x;
    float s = 0.f;
    for (int i = tid; i < FIXBLOCKS; i += 256) s += g_part[i];
    red[tid] = s;
    __syncthreads();
    for (int st = 128; st > 0; st >>= 1) {
        if (tid < st) red[tid] += red[tid + st];
        __syncthreads();
    }
    if (tid == 0 && out_size > ND) out[ND] = 1.25f * (red[0] / (float)ND);
    for (int i = ND + 1 + tid; i < out_size; i += 256) out[i] = 0.f;
}

// ---------------------------------- launch ----------------------------------
extern "C" void kernel_launch(void* const* d_in, const int* in_sizes, int n_in,
                              void* d_out, int out_size) {
    const float* x   = (const float*)d_in[0];
    const float* emb = (const float*)d_in[1];
    float* out = (float*)d_out;
    int ND = in_sizes[0];

    cudaFuncSetAttribute(vq_main_kernel,
                         cudaFuncAttributeMaxDynamicSharedMemorySize, SMEM_DYN);

    vq_split_x<<<(NROWS * DDIM / 4) / 256, 256>>>((const float4*)x, NROWS * DDIM / 4);
    vq_split_e<<<(KCODES * DDIM / 4) / 256, 256>>>((const float4*)emb, KCODES * DDIM / 4);
    vq_enorm_kernel<<<KCODES / 256, 256>>>(emb, KCODES);
    vq_main_kernel<<<NCTAS, THREADS, SMEM_DYN>>>();
    vq_fixup_kernel<<<FIXBLOCKS, 256>>>(x, emb, out);
    vq_loss_kernel<<<1, 256>>>(out, ND, out_size);
}

// round 4
// speedup vs baseline: 4.4518x; 1.1618x over previous
#include <cuda_runtime.h>
#include <cuda_bf16.h>
#include <cstdint>

// ===========================================================================
// VectorQuantizer on GB300 (sm_103 family target): split-bf16 3-pass distance
// GEMM via mma.sync.m16n8k16 + fused top-2 argmin, exact fp32 fixup.
// R4: 512 threads (16 warps, 4x4 warp grid) + pass-major MMA ordering to
// break accumulator RAW chains and fill the tensor pipe.
// ===========================================================================

#define NROWS    32768
#define DDIM     256
#define KCODES   8192
#define ROWTILE  128
#define NCTAS    (NROWS / ROWTILE)      // 256
#define NTILES   (KCODES / 128)         // 64
#define THREADS  512
#define FIXWARPS 8
#define FIXBLOCKS (NROWS / FIXWARPS)    // 4096

// SMEM layout (bytes):
//   Xhi [128][264] bf16 @ 0        (row stride 528B)   67584
//   Xlo [128][264] bf16 @ 67584                        67584
//   E ring @ 135168: stage s (0/1) at s*36864:
//       Ehi [128][72] bf16 (stride 144B) 18432, Elo +18432
#define XHI_OFF   0
#define XLO_OFF   67584
#define E_OFF     135168
#define SMEM_DYN  208896
#define SX        528     // X row stride bytes
#define SE        144     // E row stride bytes

__device__ unsigned short g_Xhi[NROWS * DDIM];
__device__ unsigned short g_Xlo[NROWS * DDIM];
__device__ unsigned short g_Ehi[KCODES * DDIM];
__device__ unsigned short g_Elo[KCODES * DDIM];
__device__ float g_enorm[KCODES];
__device__ int   g_i1[NROWS];
__device__ int   g_i2[NROWS];
__device__ float g_part[FIXBLOCKS];

// ------------------------------ PTX helpers ---------------------------------
__device__ __forceinline__ uint32_t smem_u32(const void* p) {
    uint32_t a;
    asm("{ .reg .u64 t; cvta.to.shared.u64 t, %1; cvt.u32.u64 %0, t; }"
        : "=r"(a) : "l"(p));
    return a;
}

__device__ __forceinline__ void ldsm4(uint32_t* r, uint32_t addr) {
    asm volatile("ldmatrix.sync.aligned.m8n8.x4.shared.b16 {%0,%1,%2,%3}, [%4];"
                 : "=r"(r[0]), "=r"(r[1]), "=r"(r[2]), "=r"(r[3]) : "r"(addr));
}

__device__ __forceinline__ void mma_bf16(float* d, const uint32_t* a,
                                         const uint32_t* b) {
    asm volatile(
        "mma.sync.aligned.m16n8k16.row.col.f32.bf16.bf16.f32 "
        "{%0,%1,%2,%3}, {%4,%5,%6,%7}, {%8,%9}, {%0,%1,%2,%3};"
        : "+f"(d[0]), "+f"(d[1]), "+f"(d[2]), "+f"(d[3])
        : "r"(a[0]), "r"(a[1]), "r"(a[2]), "r"(a[3]), "r"(b[0]), "r"(b[1]));
}

__device__ __forceinline__ void cpasync16(uint32_t dst, const void* src) {
    asm volatile("cp.async.cg.shared.global [%0], [%1], 16;"
                 :: "r"(dst), "l"(src));
}
#define CP_COMMIT() asm volatile("cp.async.commit_group;" ::: "memory")
#define CP_WAIT0()  asm volatile("cp.async.wait_group 0;" ::: "memory")

// top-2 insert: strict < keeps earliest index; equal value prefers lower index
__device__ __forceinline__ void t2_ins(float& v1, int& i1, float& v2, int& i2,
                                       float v, int i) {
    if (v < v1 || (v == v1 && i < i1)) { v2 = v1; i2 = i1; v1 = v; i1 = i; }
    else if (v < v2 || (v == v2 && i < i2)) { v2 = v; i2 = i; }
}

// ------------------------------- split kernels ------------------------------
__global__ void vq_split_x(const float4* __restrict__ in, int n4) {
    int i = blockIdx.x * blockDim.x + threadIdx.x;
    if (i >= n4) return;
    float4 v = in[i];
    float f[4] = {fminf(fmaxf(v.x, -1.f), 1.f), fminf(fmaxf(v.y, -1.f), 1.f),
                  fminf(fmaxf(v.z, -1.f), 1.f), fminf(fmaxf(v.w, -1.f), 1.f)};
    unsigned short h[4], l[4];
#pragma unroll
    for (int j = 0; j < 4; j++) {
        __nv_bfloat16 hb = __float2bfloat16(f[j]);
        h[j] = __bfloat16_as_ushort(hb);
        l[j] = __bfloat16_as_ushort(__float2bfloat16(f[j] - __bfloat162float(hb)));
    }
    ((uint2*)g_Xhi)[i] = make_uint2(h[0] | ((uint32_t)h[1] << 16), h[2] | ((uint32_t)h[3] << 16));
    ((uint2*)g_Xlo)[i] = make_uint2(l[0] | ((uint32_t)l[1] << 16), l[2] | ((uint32_t)l[3] << 16));
}

__global__ void vq_split_e(const float4* __restrict__ in, int n4) {
    int i = blockIdx.x * blockDim.x + threadIdx.x;
    if (i >= n4) return;
    float4 v = in[i];
    float f[4] = {v.x, v.y, v.z, v.w};
    unsigned short h[4], l[4];
#pragma unroll
    for (int j = 0; j < 4; j++) {
        __nv_bfloat16 hb = __float2bfloat16(f[j]);
        h[j] = __bfloat16_as_ushort(hb);
        l[j] = __bfloat16_as_ushort(__float2bfloat16(f[j] - __bfloat162float(hb)));
    }
    ((uint2*)g_Ehi)[i] = make_uint2(h[0] | ((uint32_t)h[1] << 16), h[2] | ((uint32_t)h[3] << 16));
    ((uint2*)g_Elo)[i] = make_uint2(l[0] | ((uint32_t)l[1] << 16), l[2] | ((uint32_t)l[3] << 16));
}

__global__ void vq_enorm_kernel(const float* __restrict__ emb, int K) {
    int k = blockIdx.x * blockDim.x + threadIdx.x;
    if (k >= K) return;
    const float4* r = (const float4*)(emb + (size_t)k * DDIM);
    float s = 0.0f;
#pragma unroll
    for (int i = 0; i < DDIM / 4; i++) {
        float4 v = r[i];
        s += v.x * v.x + v.y * v.y + v.z * v.z + v.w * v.w;
    }
    g_enorm[k] = s;
}

// --------------------------------- main kernel ------------------------------
__global__ __launch_bounds__(THREADS, 1)
void vq_main_kernel() {
    extern __shared__ char sm[];
    const uint32_t smB = smem_u32(sm);

    const int tid   = threadIdx.x;
    const int lane  = tid & 31;
    const int wid   = tid >> 5;
    const int warp_m = wid & 3;         // 0..3  (32 rows each)
    const int warp_n = wid >> 2;        // 0..3  (32 codes each)
    const int row0  = blockIdx.x * ROWTILE;

    // ---- load resident X tile (hi+lo), padded stride ----
    {
        const uint4* ph = (const uint4*)g_Xhi + (size_t)row0 * 32;
        const uint4* pl = (const uint4*)g_Xlo + (size_t)row0 * 32;
        for (int i = tid; i < 4096; i += THREADS) {
            int r = i >> 5, q = i & 31;
            *(uint4*)(sm + XHI_OFF + r * SX + q * 16) = ph[r * 32 + q];
            *(uint4*)(sm + XLO_OFF + r * SX + q * 16) = pl[r * 32 + q];
        }
    }

    // ---- cp.async E chunk issue (2048 uint4, 512 threads -> 4 each) ----
    auto issueE = [&](int stage, int t, int kc) {
#pragma unroll
        for (int j = 0; j < 4; j++) {
            int i = tid + j * THREADS;            // 0..2047
            int variant = i >> 10;                // 0=hi 1=lo
            int idx = i & 1023;
            int r = idx >> 3, q = idx & 7;
            size_t soff = ((size_t)(t * 128 + r) * DDIM + kc * 64 + q * 8) * 2;
            const char* src = (variant ? (const char*)g_Elo
                                       : (const char*)g_Ehi) + soff;
            uint32_t dst = smB + E_OFF + stage * 36864 + variant * 18432
                         + r * SE + q * 16;
            cpasync16(dst, src);
        }
        CP_COMMIT();
    };

    issueE(0, 0, 0);

    // ldmatrix address bases (bytes)
    const uint32_t aOff = (uint32_t)(warp_m * 32 + (lane & 15)) * SX
                        + ((lane >> 4) << 4);
    const uint32_t bOff = (uint32_t)(warp_n * 32 + (lane & 7) + ((lane >> 4) << 3)) * SE
                        + (((lane >> 3) & 1) << 4);

    float acc[2][4][4];
    float t2v[4][2];
    int   t2i[4][2];
#pragma unroll
    for (int r = 0; r < 4; r++) {
        t2v[r][0] = 3.4e38f; t2v[r][1] = 3.4e38f;
        t2i[r][0] = 0;       t2i[r][1] = 0;
    }

    for (int t = 0; t < NTILES; ++t) {
#pragma unroll
        for (int mt = 0; mt < 2; mt++)
#pragma unroll
            for (int nt = 0; nt < 4; nt++)
#pragma unroll
                for (int rr = 0; rr < 4; rr++) acc[mt][nt][rr] = 0.f;

        for (int kc = 0; kc < 4; ++kc) {
            int idx = t * 4 + kc;
            CP_WAIT0();
            __syncthreads();
            if (idx + 1 < NTILES * 4)
                issueE((idx + 1) & 1, (idx + 1) >> 2, (idx + 1) & 3);

            int stage = idx & 1;
            const uint32_t eHi = smB + E_OFF + stage * 36864;
            const uint32_t eLo = eHi + 18432;

#pragma unroll
            for (int ks = 0; ks < 4; ++ks) {
                uint32_t ah[2][4], al[2][4];
                uint32_t bh[4][2], bl[4][2];
                const uint32_t akb = (uint32_t)(kc * 64 + ks * 16) * 2;
#pragma unroll
                for (int mt = 0; mt < 2; mt++) {
                    ldsm4(ah[mt], smB + XHI_OFF + aOff + mt * (16 * SX) + akb);
                    ldsm4(al[mt], smB + XLO_OFF + aOff + mt * (16 * SX) + akb);
                }
#pragma unroll
                for (int ntp = 0; ntp < 2; ntp++) {
                    uint32_t r4[4];
                    ldsm4(r4, eHi + bOff + ntp * (16 * SE) + ks * 32);
                    bh[ntp * 2][0] = r4[0]; bh[ntp * 2][1] = r4[1];
                    bh[ntp * 2 + 1][0] = r4[2]; bh[ntp * 2 + 1][1] = r4[3];
                    ldsm4(r4, eLo + bOff + ntp * (16 * SE) + ks * 32);
                    bl[ntp * 2][0] = r4[0]; bl[ntp * 2][1] = r4[1];
                    bl[ntp * 2 + 1][0] = r4[2]; bl[ntp * 2 + 1][1] = r4[3];
                }
                // pass-major ordering: 8 independent MMAs between any
                // accumulator reuse (breaks the RAW chain of round 3)
#pragma unroll
                for (int mt = 0; mt < 2; mt++)
#pragma unroll
                    for (int nt = 0; nt < 4; nt++)
                        mma_bf16(acc[mt][nt], ah[mt], bh[nt]);
#pragma unroll
                for (int mt = 0; mt < 2; mt++)
#pragma unroll
                    for (int nt = 0; nt < 4; nt++)
                        mma_bf16(acc[mt][nt], al[mt], bh[nt]);
#pragma unroll
                for (int mt = 0; mt < 2; mt++)
#pragma unroll
                    for (int nt = 0; nt < 4; nt++)
                        mma_bf16(acc[mt][nt], ah[mt], bl[nt]);
            }
        }

        // ---- per-tile epilogue: score + top-2 ----
#pragma unroll
        for (int nt = 0; nt < 4; nt++) {
            int cbase = t * 128 + warp_n * 32 + nt * 8 + 2 * (lane & 3);
            float e0 = g_enorm[cbase];
            float e1 = g_enorm[cbase + 1];
#pragma unroll
            for (int mt = 0; mt < 2; mt++)
#pragma unroll
                for (int h = 0; h < 2; h++) {
                    int tr = mt * 2 + h;
                    float s0 = fmaf(-2.f, acc[mt][nt][h * 2 + 0], e0);
                    float s1 = fmaf(-2.f, acc[mt][nt][h * 2 + 1], e1);
                    t2_ins(t2v[tr][0], t2i[tr][0], t2v[tr][1], t2i[tr][1], s0, cbase);
                    t2_ins(t2v[tr][0], t2i[tr][0], t2v[tr][1], t2i[tr][1], s1, cbase + 1);
                }
        }
    }

    // ---- merge across the 4 lanes sharing each row ----
    __syncthreads();   // done with E smem; reuse as scratch
#pragma unroll
    for (int tr = 0; tr < 4; tr++) {
        float v1 = t2v[tr][0], v2 = t2v[tr][1];
        int   i1 = t2i[tr][0], i2 = t2i[tr][1];
#pragma unroll
        for (int o = 1; o <= 2; o <<= 1) {
            float w1 = __shfl_xor_sync(0xFFFFFFFFu, v1, o);
            float w2 = __shfl_xor_sync(0xFFFFFFFFu, v2, o);
            int   j1 = __shfl_xor_sync(0xFFFFFFFFu, i1, o);
            int   j2 = __shfl_xor_sync(0xFFFFFFFFu, i2, o);
            t2_ins(v1, i1, v2, i2, w1, j1);
            t2_ins(v1, i1, v2, i2, w2, j2);
        }
        if ((lane & 3) == 0) {
            int mt = tr >> 1, h = tr & 1;
            int rloc = warp_m * 32 + mt * 16 + h * 8 + (lane >> 2);
            uint4 pk;
            pk.x = __float_as_uint(v1); pk.y = (uint32_t)i1;
            pk.z = __float_as_uint(v2); pk.w = (uint32_t)i2;
            *(uint4*)(sm + E_OFF + (rloc * 4 + warp_n) * 16) = pk;
        }
    }
    __syncthreads();

    // ---- final per-row merge over 4 N-warps ----
    if (tid < ROWTILE) {
        float v1 = 3.4e38f, v2 = 3.4e38f;
        int   i1 = 0, i2 = 0;
#pragma unroll
        for (int w = 0; w < 4; w++) {
            uint4 pk = *(const uint4*)(sm + E_OFF + (tid * 4 + w) * 16);
            t2_ins(v1, i1, v2, i2, __uint_as_float(pk.x), (int)pk.y);
            t2_ins(v1, i1, v2, i2, __uint_as_float(pk.z), (int)pk.w);
        }
        g_i1[row0 + tid] = i1;
        g_i2[row0 + tid] = i2;
    }
}

// ------------------------- exact fixup + output + loss ----------------------
__global__ __launch_bounds__(256, 4)
void vq_fixup_kernel(const float* __restrict__ x, const float* __restrict__ emb,
                     float* __restrict__ out) {
    __shared__ float werr[FIXWARPS];
    int wid = threadIdx.x >> 5, lane = threadIdx.x & 31;
    int row = blockIdx.x * FIXWARPS + wid;

    const float4* xr = (const float4*)(x + (size_t)row * DDIM) + lane * 2;
    float4 xa = xr[0], xb = xr[1];
    xa.x = fminf(fmaxf(xa.x, -1.f), 1.f); xa.y = fminf(fmaxf(xa.y, -1.f), 1.f);
    xa.z = fminf(fmaxf(xa.z, -1.f), 1.f); xa.w = fminf(fmaxf(xa.w, -1.f), 1.f);
    xb.x = fminf(fmaxf(xb.x, -1.f), 1.f); xb.y = fminf(fmaxf(xb.y, -1.f), 1.f);
    xb.z = fminf(fmaxf(xb.z, -1.f), 1.f); xb.w = fminf(fmaxf(xb.w, -1.f), 1.f);

    int i1 = g_i1[row], i2 = g_i2[row];
    const float4* e1r = (const float4*)(emb + (size_t)i1 * DDIM) + lane * 2;
    const float4* e2r = (const float4*)(emb + (size_t)i2 * DDIM) + lane * 2;
    float4 e1a = e1r[0], e1b = e1r[1];
    float4 e2a = e2r[0], e2b = e2r[1];

    float p1 = 0.f, p2 = 0.f;
#define ACC(p, ev, xv) p = fmaf(ev, ev, p); p = fmaf(-2.f * (xv), ev, p)
    ACC(p1, e1a.x, xa.x); ACC(p1, e1a.y, xa.y); ACC(p1, e1a.z, xa.z); ACC(p1, e1a.w, xa.w);
    ACC(p1, e1b.x, xb.x); ACC(p1, e1b.y, xb.y); ACC(p1, e1b.z, xb.z); ACC(p1, e1b.w, xb.w);
    ACC(p2, e2a.x, xa.x); ACC(p2, e2a.y, xa.y); ACC(p2, e2a.z, xa.z); ACC(p2, e2a.w, xa.w);
    ACC(p2, e2b.x, xb.x); ACC(p2, e2b.y, xb.y); ACC(p2, e2b.z, xb.z); ACC(p2, e2b.w, xb.w);
#undef ACC
#pragma unroll
    for (int o = 16; o > 0; o >>= 1) {
        p1 += __shfl_xor_sync(0xFFFFFFFFu, p1, o);
        p2 += __shfl_xor_sync(0xFFFFFFFFu, p2, o);
    }
    bool use2 = (p2 < p1) || (p2 == p1 && i2 < i1);
    float4 qa = use2 ? e2a : e1a;
    float4 qb = use2 ? e2b : e1b;

    float err = 0.f;
    float4 oa, ob, d;
    d.x = qa.x - xa.x; d.y = qa.y - xa.y; d.z = qa.z - xa.z; d.w = qa.w - xa.w;
    oa.x = xa.x + d.x; oa.y = xa.y + d.y; oa.z = xa.z + d.z; oa.w = xa.w + d.w;
    err += d.x * d.x + d.y * d.y + d.z * d.z + d.w * d.w;
    d.x = qb.x - xb.x; d.y = qb.y - xb.y; d.z = qb.z - xb.z; d.w = qb.w - xb.w;
    ob.x = xb.x + d.x; ob.y = xb.y + d.y; ob.z = xb.z + d.z; ob.w = xb.w + d.w;
    err += d.x * d.x + d.y * d.y + d.z * d.z + d.w * d.w;

    float4* orow = (float4*)(out + (size_t)row * DDIM) + lane * 2;
    orow[0] = oa;
    orow[1] = ob;

#pragma unroll
    for (int o = 16; o > 0; o >>= 1) err += __shfl_xor_sync(0xFFFFFFFFu, err, o);
    if (lane == 0) werr[wid] = err;
    __syncthreads();
    if (threadIdx.x == 0) {
        float s = 0.f;
#pragma unroll
        for (int w = 0; w < FIXWARPS; w++) s += werr[w];
        g_part[blockIdx.x] = s;
    }
}

__global__ void vq_loss_kernel(float* __restrict__ out, int ND, int out_size) {
    __shared__ float red[256];
    int tid = threadIdx.x;
    float s = 0.f;
    for (int i = tid; i < FIXBLOCKS; i += 256) s += g_part[i];
    red[tid] = s;
    __syncthreads();
    for (int st = 128; st > 0; st >>= 1) {
        if (tid < st) red[tid] += red[tid + st];
        __syncthreads();
    }
    if (tid == 0 && out_size > ND) out[ND] = 1.25f * (red[0] / (float)ND);
    for (int i = ND + 1 + tid; i < out_size; i += 256) out[i] = 0.f;
}

// ---------------------------------- launch ----------------------------------
extern "C" void kernel_launch(void* const* d_in, const int* in_sizes, int n_in,
                              void* d_out, int out_size) {
    const float* x   = (const float*)d_in[0];
    const float* emb = (const float*)d_in[1];
    float* out = (float*)d_out;
    int ND = in_sizes[0];

    cudaFuncSetAttribute(vq_main_kernel,
                         cudaFuncAttributeMaxDynamicSharedMemorySize, SMEM_DYN);

    vq_split_x<<<(NROWS * DDIM / 4) / 256, 256>>>((const float4*)x, NROWS * DDIM / 4);
    vq_split_e<<<(KCODES * DDIM / 4) / 256, 256>>>((const float4*)emb, KCODES * DDIM / 4);
    vq_enorm_kernel<<<KCODES / 256, 256>>>(emb, KCODES);
    vq_main_kernel<<<NCTAS, THREADS, SMEM_DYN>>>();
    vq_fixup_kernel<<<FIXBLOCKS, 256>>>(x, emb, out);
    vq_loss_kernel<<<1, 256>>>(out, ND, out_size);
}